// round 4
// baseline (speedup 1.0000x reference)
#include <cuda_runtime.h>

#define U_N 100000
#define I_N 100000
#define E_N 50000
#define DD 64
#define KK 2
#define NNZ_UI_N 1600000
#define NNZ_E_N 1200000

// Scratch (no cudaMalloc allowed) — ~205 MB total.
__device__ __align__(256) float g_tu[(size_t)KK * U_N * DD];
__device__ __align__(256) float g_ti[(size_t)KK * I_N * DD];
__device__ __align__(256) float g_t [(size_t)(U_N + I_N) * DD];
__device__ __align__(256) float g_s [(size_t)(U_N + I_N) * DD];

typedef unsigned long long u64;

__device__ __forceinline__ u64 pack2(float x, float y) {
    u64 r; asm("mov.b64 %0, {%1, %2};" : "=l"(r) : "f"(x), "f"(y)); return r;
}
__device__ __forceinline__ u64 dup2(float x) {
    u64 r; asm("mov.b64 %0, {%1, %1};" : "=l"(r) : "f"(x)); return r;
}
__device__ __forceinline__ void unpack2(u64 v, float& x, float& y) {
    asm("mov.b64 {%0, %1}, %2;" : "=f"(x), "=f"(y) : "l"(v));
}
__device__ __forceinline__ u64 fma2(u64 a, u64 b, u64 c) {
    u64 d; asm("fma.rn.f32x2 %0, %1, %2, %3;" : "=l"(d) : "l"(a), "l"(b), "l"(c)); return d;
}

// ---------------------------------------------------------------------------
// Dense per-cell kernel:
//   x_row = row < nA ? featA[row] : featB[row-nA]
//   t = x @ Tw + Tb ; q = (x*x) @ Iw + Ib
//   out[row] = t   (init for the scatter; A@t + t + A@q = t + A@(t+q))
//   s[row]   = t + q
// Warp processes 8 rows; weights cached in SMEM as float2 (cols 2l,2l+1 per
// lane); x staged in SMEM as (x0, x1, x0^2, x1^2) float4, read by broadcast.
// fp32 math through packed fma.rn.f32x2 (2 FMA / instr).
// ---------------------------------------------------------------------------
#define RPW 8
__global__ void __launch_bounds__(256) gemm_tq_kernel(
    const float* __restrict__ featA, int nA,
    const float* __restrict__ featB, int nB,
    const float* __restrict__ Tw, const float* __restrict__ Tb,
    const float* __restrict__ Iw, const float* __restrict__ Ib,
    float* __restrict__ outA, float* __restrict__ outB,
    float* __restrict__ s)
{
    extern __shared__ __align__(16) char smem_raw[];
    float2* sWt = (float2*)smem_raw;             // [64][32]: (Tw[d][2l], Tw[d][2l+1])
    float2* sWi = sWt + 64 * 32;                 // [64][32] for Iw
    float4* sX  = (float4*)(smem_raw + 32768);   // [8 warps][RPW][32]

    int tid = threadIdx.x;
    const float2* Tw2 = (const float2*)Tw;
    const float2* Iw2 = (const float2*)Iw;
    for (int i = tid; i < 2048; i += 256) { sWt[i] = Tw2[i]; sWi[i] = Iw2[i]; }
    __syncthreads();

    int lane = tid & 31, wid = tid >> 5;
    int n = nA + nB;
    int r0 = (blockIdx.x * 8 + wid) * RPW;
    if (r0 >= n) return;
    float4* sx = sX + (size_t)wid * RPW * 32;

    #pragma unroll
    for (int j = 0; j < RPW; ++j) {
        int row = r0 + j;
        float2 xv = make_float2(0.f, 0.f);
        if (row < n) {
            const float* src = (row < nA) ? (featA + (size_t)row * DD)
                                          : (featB + (size_t)(row - nA) * DD);
            xv = ((const float2*)src)[lane];
        }
        sx[j * 32 + lane] = make_float4(xv.x, xv.y, xv.x * xv.x, xv.y * xv.y);
    }
    __syncwarp();

    float2 tb = ((const float2*)Tb)[lane];
    float2 ib = ((const float2*)Ib)[lane];
    u64 tacc[RPW], qacc[RPW];
    #pragma unroll
    for (int j = 0; j < RPW; ++j) { tacc[j] = pack2(tb.x, tb.y); qacc[j] = pack2(ib.x, ib.y); }

    #pragma unroll 4
    for (int p = 0; p < 32; ++p) {
        u64 w0 = *(const u64*)&sWt[(2 * p) * 32 + lane];
        u64 w1 = *(const u64*)&sWt[(2 * p + 1) * 32 + lane];
        u64 v0 = *(const u64*)&sWi[(2 * p) * 32 + lane];
        u64 v1 = *(const u64*)&sWi[(2 * p + 1) * 32 + lane];
        #pragma unroll
        for (int j = 0; j < RPW; ++j) {
            float4 xv = sx[j * 32 + p];     // broadcast LDS.128
            tacc[j] = fma2(dup2(xv.x), w0, tacc[j]);
            tacc[j] = fma2(dup2(xv.y), w1, tacc[j]);
            qacc[j] = fma2(dup2(xv.z), v0, qacc[j]);
            qacc[j] = fma2(dup2(xv.w), v1, qacc[j]);
        }
    }

    #pragma unroll
    for (int j = 0; j < RPW; ++j) {
        int row = r0 + j;
        if (row >= n) break;
        float tx, ty, qx, qy;
        unpack2(tacc[j], tx, ty);
        unpack2(qacc[j], qx, qy);
        float* orow = (row < nA) ? (outA + (size_t)row * DD)
                                 : (outB + (size_t)(row - nA) * DD);
        ((float2*)orow)[lane] = make_float2(tx, ty);
        ((float2*)(s + (size_t)row * DD))[lane] = make_float2(tx + qx, ty + qy);
    }
}

// ---------------------------------------------------------------------------
// Fused SpMM scatter:  out[r] += val * s[c]   (s = t + q, out pre-inited = t)
// 16 threads per nonzero, float4 gather + red.global.add.v4.f32 (no return).
// ---------------------------------------------------------------------------
__global__ void __launch_bounds__(256) scatter_kernel(
    const int* __restrict__ ridx, const int* __restrict__ cidx,
    const float* __restrict__ val, int nnz,
    const float* __restrict__ s,
    float* __restrict__ outA, int nA, float* __restrict__ outB)
{
    long long t = (long long)blockIdx.x * blockDim.x + threadIdx.x;
    int e = (int)(t >> 4);
    if (e >= nnz) return;
    int sub = (int)t & 15;
    int r = __ldg(ridx + e);
    int c = __ldg(cidx + e);
    float v = __ldg(val + e);
    float4 x = ((const float4*)(s + (size_t)c * DD))[sub];
    float* orow = (r < nA) ? (outA + (size_t)r * DD) : (outB + (size_t)(r - nA) * DD);
    asm volatile("red.global.add.v4.f32 [%0], {%1, %2, %3, %4};"
                 :: "l"(orow + 4 * sub),
                    "f"(v * x.x), "f"(v * x.y), "f"(v * x.z), "f"(v * x.w)
                 : "memory");
}

// ---------------------------------------------------------------------------
// Relation attention: per row n, relations r=0..2:
//   w_r = tanh(z_r @ w1 + b1) . w2 ;  beta = softmax(w) ;  out = sum beta_r z_r
// Warp per row, lane = hidden index (H=32).
// ---------------------------------------------------------------------------
__global__ void __launch_bounds__(256) att_kernel(
    const float* __restrict__ z0, const float* __restrict__ z1,
    const float* __restrict__ z2,
    const float* __restrict__ w1, const float* __restrict__ b1,
    const float* __restrict__ w2,
    float* __restrict__ out, int n)
{
    __shared__ float sw1[64 * 32];
    int tid = threadIdx.x;
    for (int i = tid; i < 2048; i += 256) sw1[i] = w1[i];
    __syncthreads();

    int lane = tid & 31;
    int row = blockIdx.x * 8 + (tid >> 5);
    if (row >= n) return;

    float bb = b1[lane], ww2 = w2[lane];
    float zlo[3], zhi[3], score[3];
    const float* zp0 = z0 + (size_t)row * DD;
    const float* zp1 = z1 + (size_t)row * DD;
    const float* zp2 = z2 + (size_t)row * DD;

    #pragma unroll
    for (int r = 0; r < 3; ++r) {
        const float* zp = (r == 0) ? zp0 : (r == 1) ? zp1 : zp2;
        zlo[r] = zp[lane];
        zhi[r] = zp[lane + 32];
        float acc = bb;
        #pragma unroll 8
        for (int d = 0; d < 32; ++d)
            acc = fmaf(__shfl_sync(0xffffffffu, zlo[r], d), sw1[d * 32 + lane], acc);
        #pragma unroll 8
        for (int d = 0; d < 32; ++d)
            acc = fmaf(__shfl_sync(0xffffffffu, zhi[r], d), sw1[(d + 32) * 32 + lane], acc);
        float term = tanhf(acc) * ww2;
        #pragma unroll
        for (int o = 16; o; o >>= 1) term += __shfl_xor_sync(0xffffffffu, term, o);
        score[r] = term;
    }

    float m = fmaxf(score[0], fmaxf(score[1], score[2]));
    float e0 = __expf(score[0] - m), e1 = __expf(score[1] - m), e2 = __expf(score[2] - m);
    float inv = 1.f / (e0 + e1 + e2);
    float b0 = e0 * inv, b1v = e1 * inv, b2 = e2 * inv;

    out[(size_t)row * DD + lane]      = b0 * zlo[0] + b1v * zlo[1] + b2 * zlo[2];
    out[(size_t)row * DD + lane + 32] = b0 * zhi[0] + b1v * zhi[1] + b2 * zhi[2];
}

static inline int cdiv(long long a, long long b) { return (int)((a + b - 1) / b); }

extern "C" void kernel_launch(void* const* d_in, const int* in_sizes, int n_in,
                              void* d_out, int out_size)
{
    const int*   u2i_idx  = (const int*)  d_in[0];
    const float* u2i_val  = (const float*)d_in[1];
    const int*   u2e_idx  = (const int*)  d_in[2];
    const float* u2e_val  = (const float*)d_in[3];
    const int*   i2e_idx  = (const int*)  d_in[4];
    const float* i2e_val  = (const float*)d_in[5];
    const float* u_feat   = (const float*)d_in[6];
    const float* i_feat   = (const float*)d_in[7];
    const float* u2e_feat = (const float*)d_in[8];
    const float* i2e_feat = (const float*)d_in[9];
    const float* Tw_u2i   = (const float*)d_in[10];
    const float* Tb_u2i   = (const float*)d_in[11];
    const float* Iw_u2i   = (const float*)d_in[12];
    const float* Ib_u2i   = (const float*)d_in[13];
    const float* Tw_u2e   = (const float*)d_in[14];
    const float* Tb_u2e   = (const float*)d_in[15];
    const float* Iw_u2e   = (const float*)d_in[16];
    const float* Ib_u2e   = (const float*)d_in[17];
    const float* Tw_i2e   = (const float*)d_in[18];
    const float* Tb_i2e   = (const float*)d_in[19];
    const float* Iw_i2e   = (const float*)d_in[20];
    const float* Ib_i2e   = (const float*)d_in[21];
    const float* uatt_w1  = (const float*)d_in[22];
    const float* uatt_b1  = (const float*)d_in[23];
    const float* uatt_w2  = (const float*)d_in[24];
    const float* iatt_w1  = (const float*)d_in[25];
    const float* iatt_b1  = (const float*)d_in[26];
    const float* iatt_w2  = (const float*)d_in[27];
    float* out = (float*)d_out;

    float *tu, *ti, *tt, *ss;
    cudaGetSymbolAddress((void**)&tu, g_tu);
    cudaGetSymbolAddress((void**)&ti, g_ti);
    cudaGetSymbolAddress((void**)&tt, g_t);
    cudaGetSymbolAddress((void**)&ss, g_s);

    cudaFuncSetAttribute(gemm_tq_kernel,
                         cudaFuncAttributeMaxDynamicSharedMemorySize, 65536);

    const size_t OFF_U2E = (size_t)(U_N + I_N) * DD;
    const size_t OFF_I2E = OFF_U2E + (size_t)KK * E_N * DD;

    // u2e cells (x = [u_feat ; u2e_feat[k]], n = U+E)
    for (int k = 0; k < KK; ++k) {
        int n = U_N + E_N;
        float* outA = tu + (size_t)k * U_N * DD;                 // rows [0,U)
        float* outB = out + OFF_U2E + (size_t)k * E_N * DD;      // rows [U,U+E) -> d_out
        gemm_tq_kernel<<<cdiv(n, 64), 256, 65536>>>(
            u_feat, U_N, u2e_feat + (size_t)k * E_N * DD, E_N,
            Tw_u2e + k * DD * DD, Tb_u2e + k * DD,
            Iw_u2e + k * DD * DD, Ib_u2e + k * DD,
            outA, outB, ss);
        const int* idx = u2e_idx + (size_t)k * 2 * NNZ_E_N;
        scatter_kernel<<<cdiv((long long)NNZ_E_N * 16, 256), 256>>>(
            idx, idx + NNZ_E_N, u2e_val + (size_t)k * NNZ_E_N, NNZ_E_N,
            ss, outA, U_N, outB);
    }
    // i2e cells (x = [i_feat ; i2e_feat[k]], n = I+E)
    for (int k = 0; k < KK; ++k) {
        int n = I_N + E_N;
        float* outA = ti + (size_t)k * I_N * DD;
        float* outB = out + OFF_I2E + (size_t)k * E_N * DD;
        gemm_tq_kernel<<<cdiv(n, 64), 256, 65536>>>(
            i_feat, I_N, i2e_feat + (size_t)k * E_N * DD, E_N,
            Tw_i2e + k * DD * DD, Tb_i2e + k * DD,
            Iw_i2e + k * DD * DD, Ib_i2e + k * DD,
            outA, outB, ss);
        const int* idx = i2e_idx + (size_t)k * 2 * NNZ_E_N;
        scatter_kernel<<<cdiv((long long)NNZ_E_N * 16, 256), 256>>>(
            idx, idx + NNZ_E_N, i2e_val + (size_t)k * NNZ_E_N, NNZ_E_N,
            ss, outA, I_N, outB);
    }
    // u2i cell (x = [u_feat ; i_feat], n = U+I)
    {
        int n = U_N + I_N;
        gemm_tq_kernel<<<cdiv(n, 64), 256, 65536>>>(
            u_feat, U_N, i_feat, I_N,
            Tw_u2i, Tb_u2i, Iw_u2i, Ib_u2i,
            tt, tt + (size_t)U_N * DD, ss);
        scatter_kernel<<<cdiv((long long)NNZ_UI_N * 16, 256), 256>>>(
            u2i_idx, u2i_idx + NNZ_UI_N, u2i_val, NNZ_UI_N,
            ss, tt, U_N, tt + (size_t)U_N * DD);
    }
    // relation attention: relations = [cell_k0, cell_k1, u2i]
    att_kernel<<<cdiv(U_N, 8), 256>>>(
        tu, tu + (size_t)U_N * DD, tt,
        uatt_w1, uatt_b1, uatt_w2, out, U_N);
    att_kernel<<<cdiv(I_N, 8), 256>>>(
        ti, ti + (size_t)I_N * DD, tt + (size_t)U_N * DD,
        iatt_w1, iatt_b1, iatt_w2, out + (size_t)U_N * DD, I_N);
}